// round 1
// baseline (speedup 1.0000x reference)
#include <cuda_runtime.h>
#include <math.h>

// Problem constants
#define BB 4
#define SS 256
#define DD 256
#define VV 128
#define EE 64
#define CC 192      // v + e
#define SC 64       // s-rows per main block
#define XSTR 68     // padded row stride (floats) for transposed x tile
#define LN_EPS 1e-3f

// ---------------- device scratch (no allocations allowed) ----------------
__device__ float g_Wall[CC * 192];          // fused [192 x 192] weight: [Wk' | Wv' | We_sub]
__device__ float g_S1k[64], g_S2k[64];
__device__ float g_S1v[64], g_S2v[64];
__device__ float g_q[BB * DD * 64];         // q per (b,d)
__device__ float g_wd[BB * DD * 64];        // V_dst @ We[128:256] per (b,d)
__device__ float g_opart[BB * DD * 4 * 64]; // per s-chunk partial attention outputs

// ---------------- prep: build fused weight matrix ----------------
__global__ void prep_wall(const float* __restrict__ g_in, const float* __restrict__ Wk,
                          const float* __restrict__ Wv, const float* __restrict__ We) {
    int c = blockIdx.x;     // 0..191
    int j = threadIdx.x;    // 0..191
    float g = g_in[c];
    float val;
    if (j < 64)        val = g * Wk[c * 64 + j];
    else if (j < 128)  val = g * Wv[c * 64 + (j - 64)];
    else {
        int t = j - 128;
        val = (c < 128) ? We[c * 64 + t] : We[(c + 128) * 64 + t];
    }
    g_Wall[c * 192 + j] = val;
}

__global__ void prep_sums(const float* __restrict__ g_in, const float* __restrict__ b_in,
                          const float* __restrict__ Wk, const float* __restrict__ bk,
                          const float* __restrict__ Wv, const float* __restrict__ bv) {
    int tid = threadIdx.x;  // 128 threads
    if (tid < 64) {
        int j = tid;
        float s1 = 0.f, s2 = 0.f;
        for (int c = 0; c < CC; c++) {
            float w = Wk[c * 64 + j];
            s1 += g_in[c] * w;
            s2 += b_in[c] * w;
        }
        g_S1k[j] = s1;
        g_S2k[j] = s2 + bk[j];
    } else {
        int j = tid - 64;
        float s1 = 0.f, s2 = 0.f;
        for (int c = 0; c < CC; c++) {
            float w = Wv[c * 64 + j];
            s1 += g_in[c] * w;
            s2 += b_in[c] * w;
        }
        g_S1v[j] = s1;
        g_S2v[j] = s2 + bv[j];
    }
}

// ---------------- per-(b,d): LN(V_dst) -> q, and wd GEMV ----------------
__global__ void __launch_bounds__(128) qwd_kernel(
    const float* __restrict__ Vdst, const float* __restrict__ g_vd,
    const float* __restrict__ b_vd, const float* __restrict__ Wq,
    const float* __restrict__ bq, const float* __restrict__ We) {
    __shared__ float vrow[VV];
    __shared__ float vn[VV];
    __shared__ float rsum[4], rsq[4];
    __shared__ float smu, srstd;

    int bd = blockIdx.x;
    int tid = threadIdx.x;
    float x = Vdst[bd * VV + tid];
    vrow[tid] = x;

    // block reduce sum / sumsq over 128
    float s = x, ss = x * x;
    for (int o = 16; o; o >>= 1) {
        s  += __shfl_down_sync(0xffffffffu, s, o);
        ss += __shfl_down_sync(0xffffffffu, ss, o);
    }
    if ((tid & 31) == 0) { rsum[tid >> 5] = s; rsq[tid >> 5] = ss; }
    __syncthreads();
    if (tid == 0) {
        float S = rsum[0] + rsum[1] + rsum[2] + rsum[3];
        float Q = rsq[0] + rsq[1] + rsq[2] + rsq[3];
        float m = S * (1.f / VV);
        float var = Q * (1.f / VV) - m * m;
        smu = m;
        srstd = rsqrtf(var + LN_EPS);
    }
    __syncthreads();
    vn[tid] = (x - smu) * srstd * g_vd[tid] + b_vd[tid];
    __syncthreads();

    if (tid < 64) {
        float q = bq[tid];
        #pragma unroll 4
        for (int j = 0; j < VV; j++) q += vn[j] * Wq[j * 64 + tid];
        g_q[bd * 64 + tid] = fmaxf(q, 0.f);
    } else {
        int t = tid - 64;
        float w = 0.f;
        #pragma unroll 4
        for (int j = 0; j < VV; j++) w += vrow[j] * We[(128 + j) * 64 + t];
        g_wd[bd * 64 + t] = w;
    }
}

// ---------------- A_new == 1.0 exactly (softmax over singleton axis) ----------------
__global__ void fill_a(float* __restrict__ outA) {
    int idx = blockIdx.x * 1024 + threadIdx.x;
    outA[idx] = 1.0f;
}

// ---------------- main fused kernel: one (b, d, s-chunk) per block ----------------
__global__ void __launch_bounds__(128) main_kernel(
    const float* __restrict__ Vsrc, const float* __restrict__ Egl,
    const float* __restrict__ A, const float* __restrict__ be,
    float* __restrict__ outE) {
    extern __shared__ float sm[];
    float* xs   = sm;                 // [192][XSTR] transposed x tile (reused as ks/vs)
    float* ks   = sm;                 // [64][65]
    float* vs   = sm + 64 * 65;       // [64][65]
    float* aval = sm + CC * XSTR;     // 64
    float* mu   = aval + 64;
    float* rstd = mu + 64;
    float* qs   = rstd + 64;
    float* wds  = qs + 64;
    float* bes  = wds + 64;
    float* scs  = bes + 64;           // [64][8]
    float* red  = scs + 512;          // 256

    int bx  = blockIdx.x;
    int scn = bx & 3;
    int d   = (bx >> 2) & 255;
    int b   = bx >> 10;
    int s0  = scn * SC;
    int bd  = b * DD + d;
    int tid = threadIdx.x;

    if (tid < 64) {
        qs[tid]  = g_q[bd * 64 + tid];
        wds[tid] = g_wd[bd * 64 + tid];
        bes[tid] = be[tid];
        aval[tid] = A[(b * SS + s0 + tid) * DD + d];
    }
    __syncthreads();

    // build transposed x tile: xs[c][r] ; x = [V_src*a (128) | E (64)]
    for (int idx = tid; idx < SC * VV; idx += 128) {
        int r = idx >> 7, j = idx & 127;
        xs[j * XSTR + r] = Vsrc[(b * SS + s0 + r) * VV + j] * aval[r];
    }
    for (int idx = tid; idx < SC * EE; idx += 128) {
        int r = idx >> 6, j = idx & 63;
        xs[(VV + j) * XSTR + r] = Egl[((size_t)(b * SS + s0 + r) * DD + d) * EE + j];
    }
    __syncthreads();

    // LayerNorm stats per row (2 threads / row)
    {
        int r = tid & 63, half = tid >> 6;
        float s = 0.f, ss = 0.f;
        int c0 = half * 96;
        for (int c = c0; c < c0 + 96; c++) {
            float x = xs[c * XSTR + r];
            s += x; ss += x * x;
        }
        red[tid] = s; red[128 + tid] = ss;
    }
    __syncthreads();
    if (tid < 64) {
        float S = red[tid] + red[tid + 64];
        float Q = red[128 + tid] + red[192 + tid];
        float m = S * (1.f / CC);
        float var = Q * (1.f / CC) - m * m;
        mu[tid] = m;
        rstd[tid] = rsqrtf(var + LN_EPS);
    }
    __syncthreads();

    // GEMM: [64 x 192] (raw x) @ [192 x 192] fused weights
    int ty = tid >> 4;        // 0..7  -> rows ty*8..ty*8+7
    int tx = tid & 15;        // 0..15 -> cols tx + 16*i, i=0..11
    int r0 = ty * 8;
    float acc[12][8];
    #pragma unroll
    for (int i = 0; i < 12; i++)
        #pragma unroll
        for (int k = 0; k < 8; k++) acc[i][k] = 0.f;

    #pragma unroll 2
    for (int c = 0; c < CC; c++) {
        float4 xa = *(const float4*)(xs + c * XSTR + r0);
        float4 xb = *(const float4*)(xs + c * XSTR + r0 + 4);
        const float* wr = g_Wall + c * 192 + tx;
        #pragma unroll
        for (int i = 0; i < 12; i++) {
            float w = __ldg(wr + i * 16);
            acc[i][0] = fmaf(xa.x, w, acc[i][0]);
            acc[i][1] = fmaf(xa.y, w, acc[i][1]);
            acc[i][2] = fmaf(xa.z, w, acc[i][2]);
            acc[i][3] = fmaf(xa.w, w, acc[i][3]);
            acc[i][4] = fmaf(xb.x, w, acc[i][4]);
            acc[i][5] = fmaf(xb.y, w, acc[i][5]);
            acc[i][6] = fmaf(xb.z, w, acc[i][6]);
            acc[i][7] = fmaf(xb.w, w, acc[i][7]);
        }
    }
    __syncthreads();  // xs reads done; reuse as ks/vs

    // E_new epilogue: cols 128..191 -> write directly (raw-x GEMM + a*wd + be, relu)
    #pragma unroll
    for (int i = 8; i < 12; i++) {
        int j = tx + (i - 8) * 16;   // e-col 0..63
        float w = wds[j], bb2 = bes[j];
        #pragma unroll
        for (int k = 0; k < 8; k++) {
            int r = r0 + k;
            float y = acc[i][k] + aval[r] * w + bb2;
            outE[((size_t)(b * SS + s0 + r) * DD + d) * EE + j] = fmaxf(y, 0.f);
        }
    }
    // k / v epilogue: unfold the LayerNorm affine, relu, stash in smem
    #pragma unroll
    for (int i = 0; i < 4; i++) {
        int j = tx + i * 16;
        float s1 = g_S1k[j], s2 = g_S2k[j];
        #pragma unroll
        for (int k = 0; k < 8; k++) {
            int r = r0 + k;
            ks[r * 65 + j] = fmaxf(rstd[r] * (acc[i][k] - mu[r] * s1) + s2, 0.f);
        }
    }
    #pragma unroll
    for (int i = 4; i < 8; i++) {
        int j = tx + (i - 4) * 16;
        float s1 = g_S1v[j], s2 = g_S2v[j];
        #pragma unroll
        for (int k = 0; k < 8; k++) {
            int r = r0 + k;
            vs[r * 65 + j] = fmaxf(rstd[r] * (acc[i][k] - mu[r] * s1) + s2, 0.f);
        }
    }
    __syncthreads();

    // scores + softmax over the 8 heads (per row)
    if (tid < 64) {
        int r = tid;
        float sc[8];
        #pragma unroll
        for (int h = 0; h < 8; h++) {
            float a = 0.f;
            #pragma unroll
            for (int p = 0; p < 8; p++) a += qs[h * 8 + p] * ks[r * 65 + h * 8 + p];
            sc[h] = a * 0.35355339059327373f;  // 1/sqrt(8)
        }
        float mx = sc[0];
        #pragma unroll
        for (int h = 1; h < 8; h++) mx = fmaxf(mx, sc[h]);
        float sum = 0.f;
        #pragma unroll
        for (int h = 0; h < 8; h++) { sc[h] = __expf(sc[h] - mx); sum += sc[h]; }
        float inv = 1.f / sum;
        #pragma unroll
        for (int h = 0; h < 8; h++) scs[r * 8 + h] = sc[h] * inv;
    }
    __syncthreads();

    // partial attention output over this s-chunk (deterministic: no atomics)
    if (tid < 64) {
        int h = tid >> 3, vv = tid & 7;
        float a = 0.f;
        #pragma unroll 4
        for (int r = 0; r < SC; r++) a += scs[r * 8 + h] * vs[r * 65 + h * 8 + vv];
        g_opart[(size_t)bx * 64 + tid] = a;
    }
}

// ---------------- finalize: V_dst_out = V_dst + relu(o @ Wo + bo) ----------------
__global__ void __launch_bounds__(128) fin_kernel(
    const float* __restrict__ Vdst, const float* __restrict__ Wo,
    const float* __restrict__ bo, float* __restrict__ outV) {
    __shared__ float os[64];
    int bd = blockIdx.x;
    int tid = threadIdx.x;
    if (tid < 64) {
        float a = 0.f;
        #pragma unroll
        for (int p = 0; p < 4; p++) a += g_opart[(size_t)(bd * 4 + p) * 64 + tid];
        os[tid] = a;
    }
    __syncthreads();
    float a = bo[tid];
    #pragma unroll 4
    for (int t = 0; t < 64; t++) a += os[t] * Wo[t * VV + tid];
    outV[bd * VV + tid] = Vdst[bd * VV + tid] + fmaxf(a, 0.f);
}

// ---------------- launch ----------------
extern "C" void kernel_launch(void* const* d_in, const int* in_sizes, int n_in,
                              void* d_out, int out_size) {
    const float* V_src = (const float*)d_in[0];
    const float* V_dst = (const float*)d_in[1];
    const float* E     = (const float*)d_in[2];
    const float* A     = (const float*)d_in[3];
    const float* g_vd  = (const float*)d_in[4];
    const float* b_vd  = (const float*)d_in[5];
    const float* g_in  = (const float*)d_in[6];
    const float* b_in  = (const float*)d_in[7];
    const float* Wq    = (const float*)d_in[8];
    const float* bq    = (const float*)d_in[9];
    const float* Wk    = (const float*)d_in[10];
    const float* bk    = (const float*)d_in[11];
    const float* Wv    = (const float*)d_in[12];
    const float* bv    = (const float*)d_in[13];
    const float* Wo    = (const float*)d_in[14];
    const float* bo    = (const float*)d_in[15];
    const float* We    = (const float*)d_in[16];
    const float* be    = (const float*)d_in[17];
    // d_in[18] = Wa, d_in[19] = ba: unused — softmax over singleton axis is exactly 1.

    float* outV = (float*)d_out;                       // [4,256,128]
    float* outE = outV + BB * DD * VV;                 // [4,256,256,64]
    float* outA = outE + (size_t)BB * SS * DD * EE;    // [4,256,256]

    const int SMEM = (CC * XSTR + 6 * 64 + 512 + 256) * (int)sizeof(float); // 56832B
    cudaFuncSetAttribute(main_kernel, cudaFuncAttributeMaxDynamicSharedMemorySize, SMEM);

    prep_wall<<<192, 192>>>(g_in, Wk, Wv, We);
    prep_sums<<<1, 128>>>(g_in, b_in, Wk, bk, Wv, bv);
    qwd_kernel<<<BB * DD, 128>>>(V_dst, g_vd, b_vd, Wq, bq, We);
    fill_a<<<(BB * SS * DD) / 1024, 1024>>>(outA);
    main_kernel<<<BB * DD * 4, 128, SMEM>>>(V_src, E, A, be, outE);
    fin_kernel<<<BB * DD, 128>>>(V_dst, Wo, bo, outV);
}

// round 2
// speedup vs baseline: 2.2647x; 2.2647x over previous
#include <cuda_runtime.h>
#include <math.h>

// Problem constants
#define BB 4
#define SS 256
#define DD 256
#define VV 128
#define EE 64
#define CC 192      // v + e
#define SC 64       // s-rows per main block
#define ESTR 68     // padded row stride for transposed E tile
#define LN_EPS 1e-3f

// ---------------- device scratch (no allocations allowed) ----------------
__device__ __align__(16) float g_Wall[CC * 192];   // fused [192 x 192] weights
__device__ float g_S1k[64], g_S2k[64];
__device__ float g_S1v[64], g_S2v[64];
__device__ float g_q[BB * DD * 64];                // q per (b,d)
__device__ float g_wd[BB * DD * 64];               // V_dst @ We[128:256] per (b,d)
__device__ float g_opart[BB * DD * 4 * 64];        // per s-chunk partial attn outputs
__device__ __align__(16) float g_G1[BB * SS * 192];// Vsrc @ Wall[0:128] per (b,s)
__device__ float g_sv[BB * SS], g_sq[BB * SS];     // Vsrc row sum / sumsq

// ---------------- prep: build fused weight matrix ----------------
__global__ void prep_wall(const float* __restrict__ g_in, const float* __restrict__ Wk,
                          const float* __restrict__ Wv, const float* __restrict__ We) {
    int c = blockIdx.x;     // 0..191
    int j = threadIdx.x;    // 0..191
    float g = g_in[c];
    float val;
    if (j < 64)        val = g * Wk[c * 64 + j];
    else if (j < 128)  val = g * Wv[c * 64 + (j - 64)];
    else {
        int t = j - 128;
        val = (c < 128) ? We[c * 64 + t] : We[(c + 128) * 64 + t];
    }
    g_Wall[c * 192 + j] = val;
}

__global__ void prep_sums(const float* __restrict__ g_in, const float* __restrict__ b_in,
                          const float* __restrict__ Wk, const float* __restrict__ bk,
                          const float* __restrict__ Wv, const float* __restrict__ bv) {
    int tid = threadIdx.x;  // 128 threads
    if (tid < 64) {
        int j = tid;
        float s1 = 0.f, s2 = 0.f;
        for (int c = 0; c < CC; c++) {
            float w = Wk[c * 64 + j];
            s1 += g_in[c] * w;
            s2 += b_in[c] * w;
        }
        g_S1k[j] = s1;
        g_S2k[j] = s2 + bk[j];
    } else {
        int j = tid - 64;
        float s1 = 0.f, s2 = 0.f;
        for (int c = 0; c < CC; c++) {
            float w = Wv[c * 64 + j];
            s1 += g_in[c] * w;
            s2 += b_in[c] * w;
        }
        g_S1v[j] = s1;
        g_S2v[j] = s2 + bv[j];
    }
}

// ---------------- G1 = Vsrc @ Wall[0:128,:]  (+ row sums for LN) ----------------
// grid = BB*SS/8 = 128 blocks, 128 threads; each block = 8 s-rows.
__global__ void __launch_bounds__(128) g1_kernel(const float* __restrict__ Vsrc) {
    extern __shared__ float sm[];
    float* xt = sm;            // [128 c][8 r]
    float* ws = sm + 1024;     // [64 c][192 n]
    int bs0 = blockIdx.x * 8;
    int tid = threadIdx.x;
    int tx = tid & 15, ty = tid >> 4;   // ty = row 0..7, tx -> 12 cols

    // load Vsrc tile transposed (coalesced reads)
    for (int idx = tid; idx < 1024; idx += 128) {
        int c = idx & 127, r = idx >> 7;
        xt[c * 8 + r] = Vsrc[(bs0 + r) * VV + c];
    }
    __syncthreads();
    if (tid < 8) {
        float s = 0.f, ss = 0.f;
        for (int c = 0; c < VV; c++) {
            float x = xt[c * 8 + tid];
            s += x; ss += x * x;
        }
        g_sv[bs0 + tid] = s;
        g_sq[bs0 + tid] = ss;
    }

    float acc[12];
    #pragma unroll
    for (int i = 0; i < 12; i++) acc[i] = 0.f;

    for (int h = 0; h < 2; h++) {
        __syncthreads();
        const float4* src = (const float4*)(g_Wall + h * 64 * 192);
        float4* dst = (float4*)ws;
        for (int idx = tid; idx < 3072; idx += 128) dst[idx] = src[idx];
        __syncthreads();
        #pragma unroll 4
        for (int c = 0; c < 64; c++) {
            float x = xt[(h * 64 + c) * 8 + ty];
            const float* wr = ws + c * 192 + tx;
            #pragma unroll
            for (int i = 0; i < 12; i++) acc[i] = fmaf(x, wr[i * 16], acc[i]);
        }
    }
    float* gout = g_G1 + (size_t)(bs0 + ty) * 192 + tx;
    #pragma unroll
    for (int i = 0; i < 12; i++) gout[i * 16] = acc[i];
}

// ---------------- per-(b,d): LN(V_dst) -> q, and wd GEMV ----------------
__global__ void __launch_bounds__(128) qwd_kernel(
    const float* __restrict__ Vdst, const float* __restrict__ g_vd,
    const float* __restrict__ b_vd, const float* __restrict__ Wq,
    const float* __restrict__ bq, const float* __restrict__ We) {
    __shared__ float vrow[VV];
    __shared__ float vn[VV];
    __shared__ float rsum[4], rsq[4];
    __shared__ float smu, srstd;

    int bd = blockIdx.x;
    int tid = threadIdx.x;
    float x = Vdst[bd * VV + tid];
    vrow[tid] = x;

    float s = x, ss = x * x;
    for (int o = 16; o; o >>= 1) {
        s  += __shfl_down_sync(0xffffffffu, s, o);
        ss += __shfl_down_sync(0xffffffffu, ss, o);
    }
    if ((tid & 31) == 0) { rsum[tid >> 5] = s; rsq[tid >> 5] = ss; }
    __syncthreads();
    if (tid == 0) {
        float S = rsum[0] + rsum[1] + rsum[2] + rsum[3];
        float Q = rsq[0] + rsq[1] + rsq[2] + rsq[3];
        float m = S * (1.f / VV);
        float var = Q * (1.f / VV) - m * m;
        smu = m;
        srstd = rsqrtf(var + LN_EPS);
    }
    __syncthreads();
    vn[tid] = (x - smu) * srstd * g_vd[tid] + b_vd[tid];
    __syncthreads();

    if (tid < 64) {
        float q = bq[tid];
        #pragma unroll 4
        for (int j = 0; j < VV; j++) q += vn[j] * Wq[j * 64 + tid];
        g_q[bd * 64 + tid] = fmaxf(q, 0.f);
    } else {
        int t = tid - 64;
        float w = 0.f;
        #pragma unroll 4
        for (int j = 0; j < VV; j++) w += vrow[j] * We[(128 + j) * 64 + t];
        g_wd[bd * 64 + t] = w;
    }
}

// ---------------- A_new == 1.0 exactly (softmax over singleton axis) ----------------
__global__ void fill_a(float* __restrict__ outA) {
    int idx = blockIdx.x * 1024 + threadIdx.x;
    outA[idx] = 1.0f;
}

// ---------------- main fused kernel: one (b, d, s-chunk) per block ----------------
// GEMM is now only K=64 (the E part); the Vsrc part comes in as a_r * G1[s,n].
__global__ void __launch_bounds__(128, 3) main_kernel(
    const float* __restrict__ Egl, const float* __restrict__ A,
    const float* __restrict__ be, float* __restrict__ outE) {
    extern __shared__ float sm[];
    float* ws   = sm;                  // [64][192] W2 tile (reused as ks/vs)
    float* ks   = sm;                  // [64][65]
    float* vs   = sm + 64 * 65;        // [64][65]
    float* es   = sm + 64 * 192;       // [64][ESTR] transposed E tile
    float* aux  = es + 64 * ESTR;
    float* aval = aux;                 // 64
    float* mu   = aval + 64;
    float* rstd = mu + 64;
    float* qs   = rstd + 64;
    float* wds  = qs + 64;
    float* bes  = wds + 64;
    float* scs  = bes + 64;            // [64][8]
    float* red  = scs + 512;           // 256

    int bx  = blockIdx.x;
    int scn = bx & 3;
    int d   = (bx >> 2) & 255;
    int b   = bx >> 10;
    int s0  = scn * SC;
    int bd  = b * DD + d;
    int tid = threadIdx.x;

    if (tid < 64) {
        qs[tid]  = g_q[bd * 64 + tid];
        wds[tid] = g_wd[bd * 64 + tid];
        bes[tid] = be[tid];
        aval[tid] = A[(b * SS + s0 + tid) * DD + d];
    }

    // stage W2 (= g_Wall rows 128..191) into smem: 3072 float4
    {
        const float4* src = (const float4*)(g_Wall + 128 * 192);
        float4* dst = (float4*)ws;
        for (int idx = tid; idx < 3072; idx += 128) dst[idx] = src[idx];
    }
    // transposed E tile: es[j][r]
    for (int idx = tid; idx < SC * EE; idx += 128) {
        int r = idx >> 6, j = idx & 63;
        es[j * ESTR + r] = Egl[((size_t)(b * SS + s0 + r) * DD + d) * EE + j];
    }
    __syncthreads();

    // LN stats per row: mu/var of [a*Vsrc | E] from precomputed Vsrc sums + E sums
    {
        int r = tid & 63, half = tid >> 6;
        float s = 0.f, ss = 0.f;
        int c0 = half * 32;
        for (int c = c0; c < c0 + 32; c++) {
            float x = es[c * ESTR + r];
            s += x; ss += x * x;
        }
        red[tid] = s; red[128 + tid] = ss;
    }
    __syncthreads();
    if (tid < 64) {
        int r = tid;
        float se  = red[r] + red[64 + r];
        float sqe = red[128 + r] + red[192 + r];
        float a  = aval[r];
        int bs = b * SS + s0 + r;
        float m   = (a * g_sv[bs] + se) * (1.f / CC);
        float msq = (a * a * g_sq[bs] + sqe) * (1.f / CC);
        mu[r] = m;
        rstd[r] = rsqrtf(msq - m * m + LN_EPS);
    }
    __syncthreads();

    // GEMM: [64 x 64] (E) @ [64 x 192] (W2, smem)
    int ty = tid >> 4;        // 0..7  -> rows ty*8..ty*8+7
    int tx = tid & 15;        // 0..15 -> cols tx + 16*i, i=0..11
    int r0 = ty * 8;
    float acc[12][8];
    #pragma unroll
    for (int i = 0; i < 12; i++)
        #pragma unroll
        for (int k = 0; k < 8; k++) acc[i][k] = 0.f;

    #pragma unroll 4
    for (int c = 0; c < EE; c++) {
        float4 xa = *(const float4*)(es + c * ESTR + r0);
        float4 xb = *(const float4*)(es + c * ESTR + r0 + 4);
        const float* wr = ws + c * 192 + tx;
        #pragma unroll
        for (int i = 0; i < 12; i++) {
            float w = wr[i * 16];
            acc[i][0] = fmaf(xa.x, w, acc[i][0]);
            acc[i][1] = fmaf(xa.y, w, acc[i][1]);
            acc[i][2] = fmaf(xa.z, w, acc[i][2]);
            acc[i][3] = fmaf(xa.w, w, acc[i][3]);
            acc[i][4] = fmaf(xb.x, w, acc[i][4]);
            acc[i][5] = fmaf(xb.y, w, acc[i][5]);
            acc[i][6] = fmaf(xb.z, w, acc[i][6]);
            acc[i][7] = fmaf(xb.w, w, acc[i][7]);
        }
    }
    __syncthreads();  // ws reads done; reuse region as ks/vs

    // E_new epilogue: cols 128..191
    #pragma unroll
    for (int i = 8; i < 12; i++) {
        int j = tx + (i - 8) * 16;   // e-col 0..63
        int n = 128 + j;
        float w = wds[j], bb2 = bes[j];
        #pragma unroll
        for (int k = 0; k < 8; k++) {
            int r = r0 + k;
            float y = aval[r] * __ldg(g_G1 + (size_t)(b * SS + s0 + r) * 192 + n)
                      + acc[i][k] + aval[r] * w + bb2;
            outE[((size_t)(b * SS + s0 + r) * DD + d) * EE + j] = fmaxf(y, 0.f);
        }
    }
    // k / v epilogue: unfold LN affine, relu, stash in smem
    #pragma unroll
    for (int i = 0; i < 4; i++) {
        int j = tx + i * 16;
        float s1 = g_S1k[j], s2 = g_S2k[j];
        #pragma unroll
        for (int k = 0; k < 8; k++) {
            int r = r0 + k;
            float yf = aval[r] * __ldg(g_G1 + (size_t)(b * SS + s0 + r) * 192 + j)
                       + acc[i][k];
            ks[r * 65 + j] = fmaxf(rstd[r] * (yf - mu[r] * s1) + s2, 0.f);
        }
    }
    #pragma unroll
    for (int i = 4; i < 8; i++) {
        int j = tx + (i - 4) * 16;
        float s1 = g_S1v[j], s2 = g_S2v[j];
        #pragma unroll
        for (int k = 0; k < 8; k++) {
            int r = r0 + k;
            float yf = aval[r] * __ldg(g_G1 + (size_t)(b * SS + s0 + r) * 192 + 64 + j)
                       + acc[i][k];
            vs[r * 65 + j] = fmaxf(rstd[r] * (yf - mu[r] * s1) + s2, 0.f);
        }
    }
    __syncthreads();

    // scores + softmax over the 8 heads (per row)
    if (tid < 64) {
        int r = tid;
        float sc[8];
        #pragma unroll
        for (int h = 0; h < 8; h++) {
            float a = 0.f;
            #pragma unroll
            for (int p = 0; p < 8; p++) a += qs[h * 8 + p] * ks[r * 65 + h * 8 + p];
            sc[h] = a * 0.35355339059327373f;  // 1/sqrt(8)
        }
        float mx = sc[0];
        #pragma unroll
        for (int h = 1; h < 8; h++) mx = fmaxf(mx, sc[h]);
        float sum = 0.f;
        #pragma unroll
        for (int h = 0; h < 8; h++) { sc[h] = __expf(sc[h] - mx); sum += sc[h]; }
        float inv = 1.f / sum;
        #pragma unroll
        for (int h = 0; h < 8; h++) scs[r * 8 + h] = sc[h] * inv;
    }
    __syncthreads();

    // partial attention output over this s-chunk (deterministic: no atomics)
    if (tid < 64) {
        int h = tid >> 3, vv = tid & 7;
        float a = 0.f;
        #pragma unroll 4
        for (int r = 0; r < SC; r++) a += scs[r * 8 + h] * vs[r * 65 + h * 8 + vv];
        g_opart[(size_t)bx * 64 + tid] = a;
    }
}

// ---------------- finalize: V_dst_out = V_dst + relu(o @ Wo + bo) ----------------
__global__ void __launch_bounds__(128) fin_kernel(
    const float* __restrict__ Vdst, const float* __restrict__ Wo,
    const float* __restrict__ bo, float* __restrict__ outV) {
    __shared__ float os[64];
    int bd = blockIdx.x;
    int tid = threadIdx.x;
    if (tid < 64) {
        float a = 0.f;
        #pragma unroll
        for (int p = 0; p < 4; p++) a += g_opart[(size_t)(bd * 4 + p) * 64 + tid];
        os[tid] = a;
    }
    __syncthreads();
    float a = bo[tid];
    #pragma unroll 4
    for (int t = 0; t < 64; t++) a += os[t] * Wo[t * VV + tid];
    outV[bd * VV + tid] = Vdst[bd * VV + tid] + fmaxf(a, 0.f);
}

// ---------------- launch ----------------
extern "C" void kernel_launch(void* const* d_in, const int* in_sizes, int n_in,
                              void* d_out, int out_size) {
    const float* V_src = (const float*)d_in[0];
    const float* V_dst = (const float*)d_in[1];
    const float* E     = (const float*)d_in[2];
    const float* A     = (const float*)d_in[3];
    const float* g_vd  = (const float*)d_in[4];
    const float* b_vd  = (const float*)d_in[5];
    const float* g_in  = (const float*)d_in[6];
    const float* b_in  = (const float*)d_in[7];
    const float* Wq    = (const float*)d_in[8];
    const float* bq    = (const float*)d_in[9];
    const float* Wk    = (const float*)d_in[10];
    const float* bk    = (const float*)d_in[11];
    const float* Wv    = (const float*)d_in[12];
    const float* bv    = (const float*)d_in[13];
    const float* Wo    = (const float*)d_in[14];
    const float* bo    = (const float*)d_in[15];
    const float* We    = (const float*)d_in[16];
    const float* be    = (const float*)d_in[17];
    // d_in[18] = Wa, d_in[19] = ba: unused — softmax over singleton axis is exactly 1.

    float* outV = (float*)d_out;                       // [4,256,128]
    float* outE = outV + BB * DD * VV;                 // [4,256,256,64]
    float* outA = outE + (size_t)BB * SS * DD * EE;    // [4,256,256]

    const int SMEM_MAIN = (64 * 192 + 64 * ESTR + 6 * 64 + 512 + 256) * (int)sizeof(float);
    const int SMEM_G1   = (1024 + 64 * 192) * (int)sizeof(float);
    cudaFuncSetAttribute(main_kernel, cudaFuncAttributeMaxDynamicSharedMemorySize, SMEM_MAIN);
    cudaFuncSetAttribute(g1_kernel, cudaFuncAttributeMaxDynamicSharedMemorySize, SMEM_G1);

    prep_wall<<<192, 192>>>(g_in, Wk, Wv, We);
    prep_sums<<<1, 128>>>(g_in, b_in, Wk, bk, Wv, bv);
    g1_kernel<<<BB * SS / 8, 128, SMEM_G1>>>(V_src);
    qwd_kernel<<<BB * DD, 128>>>(V_dst, g_vd, b_vd, Wq, bq, We);
    fill_a<<<(BB * SS * DD) / 1024, 1024>>>(outA);
    main_kernel<<<BB * DD * 4, 128, SMEM_MAIN>>>(E, A, be, outE);
    fin_kernel<<<BB * DD, 128>>>(V_dst, Wo, bo, outV);
}

// round 3
// speedup vs baseline: 2.4397x; 1.0773x over previous
#include <cuda_runtime.h>
#include <math.h>

// Problem constants
#define BB 4
#define SS 256
#define DD 256
#define VV 128
#define EE 64
#define CC 192      // v + e
#define SC 64       // s-rows per main block
#define ESTR 68     // padded row stride for transposed E tile
#define LN_EPS 1e-3f

// ---------------- device scratch (no allocations allowed) ----------------
__device__ __align__(16) float g_Wall[CC * 192];   // fused [192 x 192] weights
__device__ float g_S1k[64], g_S2k[64];
__device__ float g_S1v[64], g_S2v[64];
__device__ float g_q[BB * DD * 64];                // q per (b,d)
__device__ float g_wd[BB * DD * 64];               // V_dst @ We[128:256] per (b,d)
__device__ float g_opart[BB * DD * 4 * 64];        // per s-chunk partial attn outputs
__device__ __align__(16) float g_G1[BB * SS * 192];// Vsrc @ Wall[0:128] per (b,s)
__device__ float g_sv[BB * SS], g_sq[BB * SS];     // Vsrc row sum / sumsq

// packed fp32x2 helpers (sm_103a FFMA2 path)
__device__ __forceinline__ void fma2(unsigned long long& acc,
                                     unsigned long long x2, unsigned long long w2) {
    asm("fma.rn.f32x2 %0, %1, %2, %0;" : "+l"(acc) : "l"(x2), "l"(w2));
}
__device__ __forceinline__ unsigned long long dup2(float w) {
    unsigned long long r;
    asm("mov.b64 %0, {%1, %1};" : "=l"(r) : "f"(w));
    return r;
}
__device__ __forceinline__ float2 unpk(unsigned long long a) {
    float2 r;
    asm("mov.b64 {%0, %1}, %2;" : "=f"(r.x), "=f"(r.y) : "l"(a));
    return r;
}

// ---------------- prep: build fused weight matrix ----------------
__global__ void prep_wall(const float* __restrict__ g_in, const float* __restrict__ Wk,
                          const float* __restrict__ Wv, const float* __restrict__ We) {
    int c = blockIdx.x;     // 0..191
    int j = threadIdx.x;    // 0..191
    float g = g_in[c];
    float val;
    if (j < 64)        val = g * Wk[c * 64 + j];
    else if (j < 128)  val = g * Wv[c * 64 + (j - 64)];
    else {
        int t = j - 128;
        val = (c < 128) ? We[c * 64 + t] : We[(c + 128) * 64 + t];
    }
    g_Wall[c * 192 + j] = val;
}

__global__ void prep_sums(const float* __restrict__ g_in, const float* __restrict__ b_in,
                          const float* __restrict__ Wk, const float* __restrict__ bk,
                          const float* __restrict__ Wv, const float* __restrict__ bv) {
    int tid = threadIdx.x;  // 128 threads
    if (tid < 64) {
        int j = tid;
        float s1 = 0.f, s2 = 0.f;
        for (int c = 0; c < CC; c++) {
            float w = Wk[c * 64 + j];
            s1 += g_in[c] * w;
            s2 += b_in[c] * w;
        }
        g_S1k[j] = s1;
        g_S2k[j] = s2 + bk[j];
    } else {
        int j = tid - 64;
        float s1 = 0.f, s2 = 0.f;
        for (int c = 0; c < CC; c++) {
            float w = Wv[c * 64 + j];
            s1 += g_in[c] * w;
            s2 += b_in[c] * w;
        }
        g_S1v[j] = s1;
        g_S2v[j] = s2 + bv[j];
    }
}

// ---------------- G1 = Vsrc @ Wall[0:128,:]  (+ row sums for LN) ----------------
__global__ void __launch_bounds__(128) g1_kernel(const float* __restrict__ Vsrc) {
    extern __shared__ float sm[];
    float* xt = sm;            // [128 c][8 r]
    float* ws = sm + 1024;     // [64 c][192 n]
    int bs0 = blockIdx.x * 8;
    int tid = threadIdx.x;
    int tx = tid & 15, ty = tid >> 4;   // ty = row 0..7, tx -> 12 cols

    for (int idx = tid; idx < 1024; idx += 128) {
        int c = idx & 127, r = idx >> 7;
        xt[c * 8 + r] = Vsrc[(bs0 + r) * VV + c];
    }
    __syncthreads();
    if (tid < 8) {
        float s = 0.f, ss = 0.f;
        for (int c = 0; c < VV; c++) {
            float x = xt[c * 8 + tid];
            s += x; ss += x * x;
        }
        g_sv[bs0 + tid] = s;
        g_sq[bs0 + tid] = ss;
    }

    float acc[12];
    #pragma unroll
    for (int i = 0; i < 12; i++) acc[i] = 0.f;

    for (int h = 0; h < 2; h++) {
        __syncthreads();
        const float4* src = (const float4*)(g_Wall + h * 64 * 192);
        float4* dst = (float4*)ws;
        for (int idx = tid; idx < 3072; idx += 128) dst[idx] = src[idx];
        __syncthreads();
        #pragma unroll 4
        for (int c = 0; c < 64; c++) {
            float x = xt[(h * 64 + c) * 8 + ty];
            const float* wr = ws + c * 192 + tx;
            #pragma unroll
            for (int i = 0; i < 12; i++) acc[i] = fmaf(x, wr[i * 16], acc[i]);
        }
    }
    float* gout = g_G1 + (size_t)(bs0 + ty) * 192 + tx;
    #pragma unroll
    for (int i = 0; i < 12; i++) gout[i * 16] = acc[i];
}

// ---------------- per-(b,d): LN(V_dst) -> q, and wd GEMV ----------------
// 4 bd per block; Wq + We[128:256] staged in smem once.
__global__ void __launch_bounds__(128) qwd_kernel(
    const float* __restrict__ Vdst, const float* __restrict__ g_vd,
    const float* __restrict__ b_vd, const float* __restrict__ Wq,
    const float* __restrict__ bq, const float* __restrict__ We) {
    extern __shared__ float qsm[];
    float* wq_s = qsm;              // [128][64]
    float* we_s = qsm + 8192;       // [128][64]
    float* vn   = qsm + 16384;      // 128
    float* vrow = vn + 128;         // 128
    __shared__ float rsum[4], rsq[4], smu, srstd;

    int tid = threadIdx.x;
    for (int idx = tid; idx < 8192; idx += 128) {
        wq_s[idx] = Wq[idx];
        we_s[idx] = We[128 * 64 + idx];
    }
    float gv = g_vd[tid], bvd = b_vd[tid];
    __syncthreads();

    for (int it = 0; it < 4; it++) {
        int bd = blockIdx.x * 4 + it;
        float x = Vdst[bd * VV + tid];
        vrow[tid] = x;
        float s = x, ss = x * x;
        for (int o = 16; o; o >>= 1) {
            s  += __shfl_down_sync(0xffffffffu, s, o);
            ss += __shfl_down_sync(0xffffffffu, ss, o);
        }
        if ((tid & 31) == 0) { rsum[tid >> 5] = s; rsq[tid >> 5] = ss; }
        __syncthreads();
        if (tid == 0) {
            float S = rsum[0] + rsum[1] + rsum[2] + rsum[3];
            float Q = rsq[0] + rsq[1] + rsq[2] + rsq[3];
            float m = S * (1.f / VV);
            float var = Q * (1.f / VV) - m * m;
            smu = m;
            srstd = rsqrtf(var + LN_EPS);
        }
        __syncthreads();
        vn[tid] = (x - smu) * srstd * gv + bvd;
        __syncthreads();

        if (tid < 64) {
            float q = bq[tid];
            #pragma unroll 4
            for (int j = 0; j < VV; j++) q += vn[j] * wq_s[j * 64 + tid];
            g_q[bd * 64 + tid] = fmaxf(q, 0.f);
        } else {
            int t = tid - 64;
            float w = 0.f;
            #pragma unroll 4
            for (int j = 0; j < VV; j++) w += vrow[j] * we_s[j * 64 + t];
            g_wd[bd * 64 + t] = w;
        }
        __syncthreads();
    }
}

// ---------------- A_new == 1.0 exactly ----------------
__global__ void fill_a(float* __restrict__ outA) {
    int idx = blockIdx.x * 1024 + threadIdx.x;
    outA[idx] = 1.0f;
}

// ---------------- main fused kernel: one (b, d, s-chunk) per block ----------------
__global__ void __launch_bounds__(128, 3) main_kernel(
    const float* __restrict__ Egl, const float* __restrict__ A,
    const float* __restrict__ be, float* __restrict__ outE) {
    extern __shared__ float sm[];
    float* ws   = sm;                  // [64][192] W2 tile (reused as ks/vs)
    float* ks   = sm;                  // [64][65]
    float* vs   = sm + 64 * 65;        // [64][65]
    float* es   = sm + 64 * 192;       // [64][ESTR] transposed E tile
    float* aux  = es + 64 * ESTR;
    float* aval = aux;                 // 64
    float* mu   = aval + 64;
    float* rstd = mu + 64;
    float* qs   = rstd + 64;
    float* wds  = qs + 64;
    float* bes  = wds + 64;
    float* scs  = bes + 64;            // [64][8]
    float* red  = scs + 512;           // 256

    int bx  = blockIdx.x;
    int scn = bx & 3;
    int d   = (bx >> 2) & 255;
    int b   = bx >> 10;
    int s0  = scn * SC;
    int bd  = b * DD + d;
    int tid = threadIdx.x;

    if (tid < 64) {
        qs[tid]  = g_q[bd * 64 + tid];
        wds[tid] = g_wd[bd * 64 + tid];
        bes[tid] = be[tid];
        aval[tid] = A[(b * SS + s0 + tid) * DD + d];
    }

    // stage W2 (= g_Wall rows 128..191) into smem
    {
        const float4* src = (const float4*)(g_Wall + 128 * 192);
        float4* dst = (float4*)ws;
        for (int idx = tid; idx < 3072; idx += 128) dst[idx] = src[idx];
    }
    // transposed E tile: es[j][r]
    for (int idx = tid; idx < SC * EE; idx += 128) {
        int r = idx >> 6, j = idx & 63;
        es[j * ESTR + r] = Egl[((size_t)(b * SS + s0 + r) * DD + d) * EE + j];
    }
    __syncthreads();

    // LN stats per row from precomputed Vsrc sums + E sums
    {
        int r = tid & 63, half = tid >> 6;
        float s = 0.f, ss = 0.f;
        int c0 = half * 32;
        for (int c = c0; c < c0 + 32; c++) {
            float x = es[c * ESTR + r];
            s += x; ss += x * x;
        }
        red[tid] = s; red[128 + tid] = ss;
    }
    __syncthreads();
    if (tid < 64) {
        int r = tid;
        float se  = red[r] + red[64 + r];
        float sqe = red[128 + r] + red[192 + r];
        float a  = aval[r];
        int bs = b * SS + s0 + r;
        float m   = (a * g_sv[bs] + se) * (1.f / CC);
        float msq = (a * a * g_sq[bs] + sqe) * (1.f / CC);
        mu[r] = m;
        rstd[r] = rsqrtf(msq - m * m + LN_EPS);
    }
    __syncthreads();

    // GEMM: [64 x 64] (E) @ [64 x 192] (W2) — packed f32x2 (FFMA2), rows paired
    int ty = tid >> 4;        // 0..7  -> rows ty*8..ty*8+7
    int tx = tid & 15;        // 0..15 -> cols tx + 16*i, i=0..11
    int r0 = ty * 8;
    unsigned long long acc2[12][4];
    #pragma unroll
    for (int i = 0; i < 12; i++)
        #pragma unroll
        for (int p = 0; p < 4; p++) acc2[i][p] = 0ULL;

    #pragma unroll 4
    for (int c = 0; c < EE; c++) {
        const float* xr = es + c * ESTR + r0;
        ulonglong2 xa = *(const ulonglong2*)(xr);       // pairs (r0,r0+1),(r0+2,r0+3)
        ulonglong2 xb = *(const ulonglong2*)(xr + 4);   // pairs (r0+4,..),(r0+6,..)
        unsigned long long x2[4] = {xa.x, xa.y, xb.x, xb.y};
        const float* wr = ws + c * 192 + tx;
        #pragma unroll
        for (int i = 0; i < 12; i++) {
            unsigned long long w2 = dup2(wr[i * 16]);
            #pragma unroll
            for (int p = 0; p < 4; p++) fma2(acc2[i][p], x2[p], w2);
        }
    }
    __syncthreads();  // ws reads done; reuse region as ks/vs

    // E_new epilogue: cols 128..191
    #pragma unroll
    for (int i = 8; i < 12; i++) {
        int j = tx + (i - 8) * 16;   // e-col 0..63
        int n = 128 + j;
        float w = wds[j], bb2 = bes[j];
        #pragma unroll
        for (int p = 0; p < 4; p++) {
            float2 u = unpk(acc2[i][p]);
            int r = r0 + 2 * p;
            float y0 = aval[r] * __ldg(g_G1 + (size_t)(b * SS + s0 + r) * 192 + n)
                       + u.x + aval[r] * w + bb2;
            float y1 = aval[r + 1] * __ldg(g_G1 + (size_t)(b * SS + s0 + r + 1) * 192 + n)
                       + u.y + aval[r + 1] * w + bb2;
            outE[((size_t)(b * SS + s0 + r) * DD + d) * EE + j] = fmaxf(y0, 0.f);
            outE[((size_t)(b * SS + s0 + r + 1) * DD + d) * EE + j] = fmaxf(y1, 0.f);
        }
    }
    // k / v epilogue: unfold LN affine, relu, stash in smem
    #pragma unroll
    for (int i = 0; i < 4; i++) {
        int j = tx + i * 16;
        float s1 = g_S1k[j], s2 = g_S2k[j];
        #pragma unroll
        for (int p = 0; p < 4; p++) {
            float2 u = unpk(acc2[i][p]);
            int r = r0 + 2 * p;
            float y0 = aval[r] * __ldg(g_G1 + (size_t)(b * SS + s0 + r) * 192 + j) + u.x;
            float y1 = aval[r + 1] * __ldg(g_G1 + (size_t)(b * SS + s0 + r + 1) * 192 + j) + u.y;
            ks[r * 65 + j] = fmaxf(rstd[r] * (y0 - mu[r] * s1) + s2, 0.f);
            ks[(r + 1) * 65 + j] = fmaxf(rstd[r + 1] * (y1 - mu[r + 1] * s1) + s2, 0.f);
        }
    }
    #pragma unroll
    for (int i = 4; i < 8; i++) {
        int j = tx + (i - 4) * 16;
        float s1 = g_S1v[j], s2 = g_S2v[j];
        #pragma unroll
        for (int p = 0; p < 4; p++) {
            float2 u = unpk(acc2[i][p]);
            int r = r0 + 2 * p;
            float y0 = aval[r] * __ldg(g_G1 + (size_t)(b * SS + s0 + r) * 192 + 64 + j) + u.x;
            float y1 = aval[r + 1] * __ldg(g_G1 + (size_t)(b * SS + s0 + r + 1) * 192 + 64 + j) + u.y;
            vs[r * 65 + j] = fmaxf(rstd[r] * (y0 - mu[r] * s1) + s2, 0.f);
            vs[(r + 1) * 65 + j] = fmaxf(rstd[r + 1] * (y1 - mu[r + 1] * s1) + s2, 0.f);
        }
    }
    __syncthreads();

    // scores + softmax over the 8 heads (per row)
    if (tid < 64) {
        int r = tid;
        float sc[8];
        #pragma unroll
        for (int h = 0; h < 8; h++) {
            float a = 0.f;
            #pragma unroll
            for (int p = 0; p < 8; p++) a += qs[h * 8 + p] * ks[r * 65 + h * 8 + p];
            sc[h] = a * 0.35355339059327373f;  // 1/sqrt(8)
        }
        float mx = sc[0];
        #pragma unroll
        for (int h = 1; h < 8; h++) mx = fmaxf(mx, sc[h]);
        float sum = 0.f;
        #pragma unroll
        for (int h = 0; h < 8; h++) { sc[h] = __expf(sc[h] - mx); sum += sc[h]; }
        float inv = 1.f / sum;
        #pragma unroll
        for (int h = 0; h < 8; h++) scs[r * 8 + h] = sc[h] * inv;
    }
    __syncthreads();

    // partial attention output over this s-chunk (deterministic: no atomics)
    if (tid < 64) {
        int h = tid >> 3, vv = tid & 7;
        float a = 0.f;
        #pragma unroll 4
        for (int r = 0; r < SC; r++) a += scs[r * 8 + h] * vs[r * 65 + h * 8 + vv];
        g_opart[(size_t)bx * 64 + tid] = a;
    }
}

// ---------------- finalize: V_dst_out = V_dst + relu(o @ Wo + bo) ----------------
// 4 bd per block; Wo staged in smem once.
__global__ void __launch_bounds__(128) fin_kernel(
    const float* __restrict__ Vdst, const float* __restrict__ Wo,
    const float* __restrict__ bo, float* __restrict__ outV) {
    extern __shared__ float fsm[];
    float* wo_s = fsm;          // [64][128]
    float* os   = fsm + 8192;   // 64
    int tid = threadIdx.x;
    for (int idx = tid; idx < 8192; idx += 128) wo_s[idx] = Wo[idx];
    float bof = bo[tid];
    __syncthreads();

    for (int it = 0; it < 4; it++) {
        int bd = blockIdx.x * 4 + it;
        if (tid < 64) {
            float a = 0.f;
            #pragma unroll
            for (int p = 0; p < 4; p++) a += g_opart[(size_t)(bd * 4 + p) * 64 + tid];
            os[tid] = a;
        }
        __syncthreads();
        float a = bof;
        #pragma unroll 4
        for (int t = 0; t < 64; t++) a += os[t] * wo_s[t * VV + tid];
        outV[bd * VV + tid] = Vdst[bd * VV + tid] + fmaxf(a, 0.f);
        __syncthreads();
    }
}

// ---------------- launch ----------------
extern "C" void kernel_launch(void* const* d_in, const int* in_sizes, int n_in,
                              void* d_out, int out_size) {
    const float* V_src = (const float*)d_in[0];
    const float* V_dst = (const float*)d_in[1];
    const float* E     = (const float*)d_in[2];
    const float* A     = (const float*)d_in[3];
    const float* g_vd  = (const float*)d_in[4];
    const float* b_vd  = (const float*)d_in[5];
    const float* g_in  = (const float*)d_in[6];
    const float* b_in  = (const float*)d_in[7];
    const float* Wq    = (const float*)d_in[8];
    const float* bq    = (const float*)d_in[9];
    const float* Wk    = (const float*)d_in[10];
    const float* bk    = (const float*)d_in[11];
    const float* Wv    = (const float*)d_in[12];
    const float* bv    = (const float*)d_in[13];
    const float* Wo    = (const float*)d_in[14];
    const float* bo    = (const float*)d_in[15];
    const float* We    = (const float*)d_in[16];
    const float* be    = (const float*)d_in[17];
    // d_in[18] = Wa, d_in[19] = ba: unused — softmax over singleton axis is exactly 1.

    float* outV = (float*)d_out;                       // [4,256,128]
    float* outE = outV + BB * DD * VV;                 // [4,256,256,64]
    float* outA = outE + (size_t)BB * SS * DD * EE;    // [4,256,256]

    const int SMEM_MAIN = (64 * 192 + 64 * ESTR + 6 * 64 + 512 + 256) * (int)sizeof(float);
    const int SMEM_G1   = (1024 + 64 * 192) * (int)sizeof(float);
    const int SMEM_QWD  = (16384 + 256) * (int)sizeof(float);
    const int SMEM_FIN  = (8192 + 64) * (int)sizeof(float);
    cudaFuncSetAttribute(main_kernel, cudaFuncAttributeMaxDynamicSharedMemorySize, SMEM_MAIN);
    cudaFuncSetAttribute(g1_kernel, cudaFuncAttributeMaxDynamicSharedMemorySize, SMEM_G1);
    cudaFuncSetAttribute(qwd_kernel, cudaFuncAttributeMaxDynamicSharedMemorySize, SMEM_QWD);
    cudaFuncSetAttribute(fin_kernel, cudaFuncAttributeMaxDynamicSharedMemorySize, SMEM_FIN);

    prep_wall<<<192, 192>>>(g_in, Wk, Wv, We);
    prep_sums<<<1, 128>>>(g_in, b_in, Wk, bk, Wv, bv);
    g1_kernel<<<BB * SS / 8, 128, SMEM_G1>>>(V_src);
    qwd_kernel<<<BB * DD / 4, 128, SMEM_QWD>>>(V_dst, g_vd, b_vd, Wq, bq, We);
    fill_a<<<(BB * SS * DD) / 1024, 1024>>>(outA);
    main_kernel<<<BB * DD * 4, 128, SMEM_MAIN>>>(E, A, be, outE);
    fin_kernel<<<BB * DD / 4, 128, SMEM_FIN>>>(V_dst, Wo, bo, outV);
}